// round 5
// baseline (speedup 1.0000x reference)
#include <cuda_runtime.h>
#include <cuda_bf16.h>

#define B_DIM 512
#define P_DIM 512
#define F_DIM 1024
#define EPS_T 1e-8f

#define SPLITK 16
#define KC 64                 // k-extent per work unit
#define BK 32                 // k per smem tile (2 tiles per unit)
#define BM 64
#define BN 64
#define NTILES 64             // 8 x 8 output tiles
#define NUNITS (NTILES * SPLITK)   // 1024
#define GRID_MAIN 444
#define KPAD 36               // smem row pitch (floats): 16B-aligned, good banks

// Scratch (static device globals — no allocation allowed)
__device__ float g_xs[B_DIM * F_DIM];             // sigmoid(x), row-major
__device__ float g_ws[P_DIM * F_DIM];             // sigmoid(w), row-major
__device__ float g_Spart[4][B_DIM + P_DIM];       // quarter-row sigmoid sums
__device__ float g_part[SPLITK * B_DIM * P_DIM];  // split-K partials (16 MB, L2)
__device__ int   g_ctr;                           // dynamic work counter

// ---------------------------------------------------------------------------
// Kernel 1: streaming sigmoid (row-major, no transpose) + quarter-row sums.
// One warp per quarter-row (64 floats... 64 float4? quarter-row = 256 floats
// = 64 float4; 32 lanes x 2 float4). grid 512 x 256 threads. Also resets g_ctr.
// ---------------------------------------------------------------------------
__global__ __launch_bounds__(256) void prep_kernel(
    const float* __restrict__ x, const float* __restrict__ w)
{
    if (blockIdx.x == 0 && threadIdx.x == 0) g_ctr = 0;

    int warp = threadIdx.x >> 5;
    int lane = threadIdx.x & 31;
    int q = blockIdx.x * 8 + warp;        // 0..4095 quarter-row id
    int row = q >> 2;                     // 0..1023 combined row
    int quarter = q & 3;

    const float* src;
    float* dst;
    if (row < B_DIM) {
        src = x + (size_t)row * F_DIM;
        dst = g_xs + (size_t)row * F_DIM;
    } else {
        src = w + (size_t)(row - B_DIM) * F_DIM;
        dst = g_ws + (size_t)(row - B_DIM) * F_DIM;
    }

    int f4 = quarter * 64 + lane;         // float4 index within row
    float4 a = *reinterpret_cast<const float4*>(src + f4 * 4);
    float4 b = *reinterpret_cast<const float4*>(src + (f4 + 32) * 4);

    float s0 = 1.0f / (1.0f + __expf(-a.x));
    float s1 = 1.0f / (1.0f + __expf(-a.y));
    float s2 = 1.0f / (1.0f + __expf(-a.z));
    float s3 = 1.0f / (1.0f + __expf(-a.w));
    float s4 = 1.0f / (1.0f + __expf(-b.x));
    float s5 = 1.0f / (1.0f + __expf(-b.y));
    float s6 = 1.0f / (1.0f + __expf(-b.z));
    float s7 = 1.0f / (1.0f + __expf(-b.w));

    *reinterpret_cast<float4*>(dst + f4 * 4)        = make_float4(s0, s1, s2, s3);
    *reinterpret_cast<float4*>(dst + (f4 + 32) * 4) = make_float4(s4, s5, s6, s7);

    float local = ((s0 + s1) + (s2 + s3)) + ((s4 + s5) + (s6 + s7));
    #pragma unroll
    for (int o = 16; o > 0; o >>= 1)
        local += __shfl_xor_sync(0xFFFFFFFFu, local, o);
    if (lane == 0)
        g_Spart[quarter][row] = local;
}

// ---------------------------------------------------------------------------
// Main-kernel compute step: one BK=32 tile from smem buffer.
// Register tile: m = ty + 16*i, n = tx + 16*j (strided).
// ---------------------------------------------------------------------------
__device__ __forceinline__ void compute_tile(
    const float (*xsb)[KPAD], const float (*wsb)[KPAD],
    int tx, int ty, float acc[4][4])
{
    #pragma unroll 4
    for (int k4 = 0; k4 < 8; k4++) {
        float4 xv[4], wv[4];
        #pragma unroll
        for (int i = 0; i < 4; i++)
            xv[i] = *reinterpret_cast<const float4*>(&xsb[ty + 16 * i][k4 * 4]);
        #pragma unroll
        for (int j = 0; j < 4; j++)
            wv[j] = *reinterpret_cast<const float4*>(&wsb[tx + 16 * j][k4 * 4]);

        #pragma unroll
        for (int i = 0; i < 4; i++)
            #pragma unroll
            for (int j = 0; j < 4; j++) {
                float m0 = fminf(xv[i].x, wv[j].x);
                float m1 = fminf(xv[i].y, wv[j].y);
                float m2 = fminf(xv[i].z, wv[j].z);
                float m3 = fminf(xv[i].w, wv[j].w);
                acc[i][j] += (m0 + m1) + (m2 + m3);
            }
    }
}

// ---------------------------------------------------------------------------
// Kernel 2: persistent pairwise min-sum with dynamic work queue.
// Unit = 64x64 output tile x KC=64 k-slice. 1024 units total.
// ---------------------------------------------------------------------------
__global__ __launch_bounds__(256) void tversky_main_kernel()
{
    __shared__ float xs[2][BM][KPAD];
    __shared__ float ws[2][BN][KPAD];
    __shared__ int s_u;

    int tid = threadIdx.x;
    int tx = tid & 15;
    int ty = tid >> 4;
    int lrow = tid >> 3;       // 0..31 (loader row; also handles lrow+32)
    int kq = tid & 7;          // 0..7 (loader k-quad)

    if (tid == 0) s_u = atomicAdd(&g_ctr, 1);
    __syncthreads();
    int u = s_u;

    while (u < NUNITS) {
        int tile  = u >> 4;
        int split = u & 15;
        int m0 = (tile >> 3) * BM;
        int n0 = (tile & 7) * BN;
        int kbase = split * KC;

        const float* xg = g_xs + (size_t)(m0 + lrow) * F_DIM + kbase + kq * 4;
        const float* wg = g_ws + (size_t)(n0 + lrow) * F_DIM + kbase + kq * 4;

        // ---- load tile 0 (k 0..31 of this unit) into buf 0
        float4 ax0 = *reinterpret_cast<const float4*>(xg);
        float4 ax1 = *reinterpret_cast<const float4*>(xg + 32 * F_DIM);
        float4 aw0 = *reinterpret_cast<const float4*>(wg);
        float4 aw1 = *reinterpret_cast<const float4*>(wg + 32 * F_DIM);
        *reinterpret_cast<float4*>(&xs[0][lrow][kq * 4])      = ax0;
        *reinterpret_cast<float4*>(&xs[0][lrow + 32][kq * 4]) = ax1;
        *reinterpret_cast<float4*>(&ws[0][lrow][kq * 4])      = aw0;
        *reinterpret_cast<float4*>(&ws[0][lrow + 32][kq * 4]) = aw1;

        if (tid == 0) s_u = atomicAdd(&g_ctr, 1);   // fetch next unit (hidden)
        __syncthreads();
        int u_next = s_u;

        // ---- prefetch tile 1 (k 32..63) into regs
        float4 bx0 = *reinterpret_cast<const float4*>(xg + 32);
        float4 bx1 = *reinterpret_cast<const float4*>(xg + 32 * F_DIM + 32);
        float4 bw0 = *reinterpret_cast<const float4*>(wg + 32);
        float4 bw1 = *reinterpret_cast<const float4*>(wg + 32 * F_DIM + 32);

        float acc[4][4];
        #pragma unroll
        for (int i = 0; i < 4; i++)
            #pragma unroll
            for (int j = 0; j < 4; j++) acc[i][j] = 0.f;

        compute_tile(xs[0], ws[0], tx, ty, acc);

        *reinterpret_cast<float4*>(&xs[1][lrow][kq * 4])      = bx0;
        *reinterpret_cast<float4*>(&xs[1][lrow + 32][kq * 4]) = bx1;
        *reinterpret_cast<float4*>(&ws[1][lrow][kq * 4])      = bw0;
        *reinterpret_cast<float4*>(&ws[1][lrow + 32][kq * 4]) = bw1;
        __syncthreads();

        compute_tile(xs[1], ws[1], tx, ty, acc);

        // ---- write split-K partials (L2-resident)
        float* pb = g_part + ((size_t)split * B_DIM + m0) * P_DIM + n0;
        #pragma unroll
        for (int i = 0; i < 4; i++)
            #pragma unroll
            for (int j = 0; j < 4; j++)
                pb[(size_t)(ty + 16 * i) * P_DIM + tx + 16 * j] = acc[i][j];

        u = u_next;
        __syncthreads();   // protects s_u and smem reuse across units
    }
}

// ---------------------------------------------------------------------------
// Kernel 3: combine 16 split-K partials + rowsums, Tversky epilogue.
//   out = I / (I + alpha*(Sx-I) + beta*(Sw-I) + eps) + bias
// float4 per thread. 256 blocks x 256 threads.
// ---------------------------------------------------------------------------
__global__ __launch_bounds__(256) void finalize_kernel(
    const float* __restrict__ bias,
    const float* __restrict__ alpha,
    const float* __restrict__ beta,
    float* __restrict__ out)
{
    int t4 = blockIdx.x * 256 + threadIdx.x;   // 0..65535 (float4 id)
    int m  = t4 >> 7;                          // 128 float4 per output row
    int n4 = t4 & 127;

    const float4* pp = reinterpret_cast<const float4*>(g_part) + t4;
    float4 I = make_float4(0.f, 0.f, 0.f, 0.f);
    #pragma unroll
    for (int s = 0; s < SPLITK; s++) {
        float4 v = pp[(size_t)s * (B_DIM * P_DIM / 4)];
        I.x += v.x; I.y += v.y; I.z += v.z; I.w += v.w;
    }

    float Sx = g_Spart[0][m] + g_Spart[1][m] + g_Spart[2][m] + g_Spart[3][m];

    float4 Sw = make_float4(0.f, 0.f, 0.f, 0.f);
    #pragma unroll
    for (int q = 0; q < 4; q++) {
        float4 v = *reinterpret_cast<const float4*>(&g_Spart[q][B_DIM + n4 * 4]);
        Sw.x += v.x; Sw.y += v.y; Sw.z += v.z; Sw.w += v.w;
    }

    float a = *alpha;
    float b = *beta;
    float4 bs = *reinterpret_cast<const float4*>(bias + n4 * 4);

    float4 o;
    o.x = I.x / (I.x + a * (Sx - I.x) + b * (Sw.x - I.x) + EPS_T) + bs.x;
    o.y = I.y / (I.y + a * (Sx - I.y) + b * (Sw.y - I.y) + EPS_T) + bs.y;
    o.z = I.z / (I.z + a * (Sx - I.z) + b * (Sw.z - I.z) + EPS_T) + bs.z;
    o.w = I.w / (I.w + a * (Sx - I.w) + b * (Sw.w - I.w) + EPS_T) + bs.w;

    *(reinterpret_cast<float4*>(out) + t4) = o;
}

// ---------------------------------------------------------------------------
extern "C" void kernel_launch(void* const* d_in, const int* in_sizes, int n_in,
                              void* d_out, int out_size)
{
    const float* x      = (const float*)d_in[0];   // (512, 1024)
    const float* weight = (const float*)d_in[1];   // (512, 1024)
    const float* bias   = (const float*)d_in[2];   // (512,)
    const float* alpha  = (const float*)d_in[3];   // scalar
    const float* beta   = (const float*)d_in[4];   // scalar
    float* out = (float*)d_out;                    // (512, 512)

    prep_kernel<<<512, 256>>>(x, weight);
    tversky_main_kernel<<<GRID_MAIN, 256>>>();
    finalize_kernel<<<(B_DIM * P_DIM / 4) / 256, 256>>>(bias, alpha, beta, out);
}

// round 7
// speedup vs baseline: 1.4286x; 1.4286x over previous
#include <cuda_runtime.h>
#include <cuda_bf16.h>

#define B_DIM 512
#define P_DIM 512
#define F_DIM 1024
#define EPS_T 1e-8f

#define SPLITK 16
#define KC 64                  // u16 k-extent per work unit (one smem tile)
#define NTILES 64              // 8 x 8 output tiles of 64x64
#define NUNITS (NTILES * SPLITK)   // 1024
#define GRID_MAIN 296
#define QSCALE 65535.0f
#define KPITCH 72              // smem row pitch in u16 (144B: conflict-free)

// Scratch (static device globals — no allocation allowed)
__device__ __align__(16) unsigned short g_qx[B_DIM * F_DIM];  // u16 sigmoid(x)
__device__ __align__(16) unsigned short g_qw[P_DIM * F_DIM];  // u16 sigmoid(w)
__device__ __align__(16) float g_S[B_DIM + P_DIM];            // fp32 row sums
__device__ float g_part[SPLITK * B_DIM * P_DIM];              // split-K partials
__device__ int   g_ctr;                                       // work counter

// ---------------------------------------------------------------------------
// Kernel 1: streaming sigmoid -> u16 quantize + exact fp32 row sums.
// One block per row (1024 blocks x 256 threads, 4 floats/thread).
// Also resets the work counter for the main kernel.
// ---------------------------------------------------------------------------
__global__ __launch_bounds__(256) void prep_kernel(
    const float* __restrict__ x, const float* __restrict__ w)
{
    if (blockIdx.x == 0 && threadIdx.x == 0) g_ctr = 0;

    int row = blockIdx.x;                 // 0..1023 combined
    int tid = threadIdx.x;

    const float* src;
    unsigned short* dstq;
    if (row < B_DIM) {
        src  = x + (size_t)row * F_DIM;
        dstq = g_qx + (size_t)row * F_DIM;
    } else {
        src  = w + (size_t)(row - B_DIM) * F_DIM;
        dstq = g_qw + (size_t)(row - B_DIM) * F_DIM;
    }

    float4 v = reinterpret_cast<const float4*>(src)[tid];
    float s0 = 1.0f / (1.0f + __expf(-v.x));
    float s1 = 1.0f / (1.0f + __expf(-v.y));
    float s2 = 1.0f / (1.0f + __expf(-v.z));
    float s3 = 1.0f / (1.0f + __expf(-v.w));

    unsigned q0 = __float2uint_rn(s0 * QSCALE);
    unsigned q1 = __float2uint_rn(s1 * QSCALE);
    unsigned q2 = __float2uint_rn(s2 * QSCALE);
    unsigned q3 = __float2uint_rn(s3 * QSCALE);
    reinterpret_cast<uint2*>(dstq)[tid] = make_uint2(q0 | (q1 << 16), q2 | (q3 << 16));

    float local = (s0 + s1) + (s2 + s3);
    #pragma unroll
    for (int o = 16; o > 0; o >>= 1)
        local += __shfl_xor_sync(0xFFFFFFFFu, local, o);

    __shared__ float red[8];
    if ((tid & 31) == 0) red[tid >> 5] = local;
    __syncthreads();
    if (tid == 0) {
        float t = 0.f;
        #pragma unroll
        for (int i = 0; i < 8; i++) t += red[i];
        g_S[row] = t;
    }
}

// ---------------------------------------------------------------------------
// Kernel 2: persistent u16 min-sum, dynamic queue, cross-unit double buffer.
// Unit = 64x64 output tile x KC=64 k-slice; inner math = vminu2 + dp2a.
// ---------------------------------------------------------------------------
__global__ __launch_bounds__(256, 2) void tversky_main_kernel()
{
    __shared__ unsigned short xs[2][64][KPITCH];
    __shared__ unsigned short ws[2][64][KPITCH];
    __shared__ int s_u;

    int tid = threadIdx.x;
    int tx = tid & 15;            // N direction
    int ty = tid >> 4;            // M direction
    int r0 = tid >> 3;            // loader row 0..31 (also handles r0+32)
    int seg = tid & 7;            // 16B segment within 128B row

    const uint4* xg4 = reinterpret_cast<const uint4*>(g_qx);
    const uint4* wg4 = reinterpret_cast<const uint4*>(g_qw);

    if (tid == 0) s_u = atomicAdd(&g_ctr, 1);
    __syncthreads();
    int u = s_u;

    if (u < NUNITS) {             // prologue: load first tile into buf 0
        int tile = u >> 4, split = u & 15;
        int m0 = (tile >> 3) << 6, n0 = (tile & 7) << 6;
        int kb4 = split << 3;     // uint4 offset within a 128-uint4 row
        uint4 a0 = xg4[(size_t)(m0 + r0) * 128 + kb4 + seg];
        uint4 a1 = xg4[(size_t)(m0 + r0 + 32) * 128 + kb4 + seg];
        uint4 b0 = wg4[(size_t)(n0 + r0) * 128 + kb4 + seg];
        uint4 b1 = wg4[(size_t)(n0 + r0 + 32) * 128 + kb4 + seg];
        *reinterpret_cast<uint4*>(&xs[0][r0][seg * 8])      = a0;
        *reinterpret_cast<uint4*>(&xs[0][r0 + 32][seg * 8]) = a1;
        *reinterpret_cast<uint4*>(&ws[0][r0][seg * 8])      = b0;
        *reinterpret_cast<uint4*>(&ws[0][r0 + 32][seg * 8]) = b1;
    }
    int cur = 0;

    while (u < NUNITS) {
        if (tid == 0) s_u = atomicAdd(&g_ctr, 1);
        __syncthreads();          // tile(cur) visible; s_u visible
        int un = s_u;

        // prefetch next unit's tile into registers (latency hidden by compute)
        uint4 a0, a1, b0, b1;
        if (un < NUNITS) {
            int tile = un >> 4, split = un & 15;
            int m0 = (tile >> 3) << 6, n0 = (tile & 7) << 6;
            int kb4 = split << 3;
            a0 = xg4[(size_t)(m0 + r0) * 128 + kb4 + seg];
            a1 = xg4[(size_t)(m0 + r0 + 32) * 128 + kb4 + seg];
            b0 = wg4[(size_t)(n0 + r0) * 128 + kb4 + seg];
            b1 = wg4[(size_t)(n0 + r0 + 32) * 128 + kb4 + seg];
        }

        unsigned acc[4][4];
        #pragma unroll
        for (int i = 0; i < 4; i++)
            #pragma unroll
            for (int j = 0; j < 4; j++) acc[i][j] = 0u;

        const unsigned short (*xb)[KPITCH] = xs[cur];
        const unsigned short (*wb)[KPITCH] = ws[cur];

        #pragma unroll 2
        for (int c = 0; c < 8; c++) {       // 8 u16 per chunk
            uint4 xq[4], wq[4];
            #pragma unroll
            for (int i = 0; i < 4; i++)
                xq[i] = *reinterpret_cast<const uint4*>(&xb[ty + 16 * i][c * 8]);
            #pragma unroll
            for (int j = 0; j < 4; j++)
                wq[j] = *reinterpret_cast<const uint4*>(&wb[tx + 16 * j][c * 8]);

            #pragma unroll
            for (int i = 0; i < 4; i++)
                #pragma unroll
                for (int j = 0; j < 4; j++) {
                    acc[i][j] = __dp2a_lo(__vminu2(xq[i].x, wq[j].x), 0x0101u, acc[i][j]);
                    acc[i][j] = __dp2a_lo(__vminu2(xq[i].y, wq[j].y), 0x0101u, acc[i][j]);
                    acc[i][j] = __dp2a_lo(__vminu2(xq[i].z, wq[j].z), 0x0101u, acc[i][j]);
                    acc[i][j] = __dp2a_lo(__vminu2(xq[i].w, wq[j].w), 0x0101u, acc[i][j]);
                }
        }

        if (un < NUNITS) {        // stage next tile into the other buffer
            int nb = cur ^ 1;
            *reinterpret_cast<uint4*>(&xs[nb][r0][seg * 8])      = a0;
            *reinterpret_cast<uint4*>(&xs[nb][r0 + 32][seg * 8]) = a1;
            *reinterpret_cast<uint4*>(&ws[nb][r0][seg * 8])      = b0;
            *reinterpret_cast<uint4*>(&ws[nb][r0 + 32][seg * 8]) = b1;
        }

        // write split-K partials for unit u (exact integer counts as fp32)
        {
            int tile = u >> 4, split = u & 15;
            int m0 = (tile >> 3) << 6, n0 = (tile & 7) << 6;
            float* pb = g_part + ((size_t)split * B_DIM + m0) * P_DIM + n0;
            #pragma unroll
            for (int i = 0; i < 4; i++)
                #pragma unroll
                for (int j = 0; j < 4; j++)
                    pb[(size_t)(ty + 16 * i) * P_DIM + tx + 16 * j] = (float)acc[i][j];
        }

        u = un;
        cur ^= 1;
        __syncthreads();          // protect s_u and buffer reuse
    }
}

// ---------------------------------------------------------------------------
// Kernel 3: combine 16 split-K partials (scale 1/65535) + Tversky epilogue.
//   out = I / (I + alpha*(Sx-I) + beta*(Sw-I) + eps) + bias
// ---------------------------------------------------------------------------
__global__ __launch_bounds__(256) void finalize_kernel(
    const float* __restrict__ bias,
    const float* __restrict__ alpha,
    const float* __restrict__ beta,
    float* __restrict__ out)
{
    int t4 = blockIdx.x * 256 + threadIdx.x;   // float4 id, 0..65535
    int m  = t4 >> 7;
    int n4 = t4 & 127;

    const float4* pp = reinterpret_cast<const float4*>(g_part) + t4;
    float4 I = make_float4(0.f, 0.f, 0.f, 0.f);
    #pragma unroll
    for (int s = 0; s < SPLITK; s++) {
        float4 v = pp[(size_t)s * (B_DIM * P_DIM / 4)];
        I.x += v.x; I.y += v.y; I.z += v.z; I.w += v.w;
    }
    const float inv = 1.0f / QSCALE;
    I.x *= inv; I.y *= inv; I.z *= inv; I.w *= inv;

    float Sx = g_S[m];
    float4 Sw = reinterpret_cast<const float4*>(g_S + B_DIM)[n4];

    float a = *alpha;
    float b = *beta;
    float4 bs = reinterpret_cast<const float4*>(bias)[n4];

    float4 o;
    o.x = I.x / (I.x + a * (Sx - I.x) + b * (Sw.x - I.x) + EPS_T) + bs.x;
    o.y = I.y / (I.y + a * (Sx - I.y) + b * (Sw.y - I.y) + EPS_T) + bs.y;
    o.z = I.z / (I.z + a * (Sx - I.z) + b * (Sw.z - I.z) + EPS_T) + bs.z;
    o.w = I.w / (I.w + a * (Sx - I.w) + b * (Sw.w - I.w) + EPS_T) + bs.w;

    reinterpret_cast<float4*>(out)[t4] = o;
}

// ---------------------------------------------------------------------------
extern "C" void kernel_launch(void* const* d_in, const int* in_sizes, int n_in,
                              void* d_out, int out_size)
{
    const float* x      = (const float*)d_in[0];   // (512, 1024)
    const float* weight = (const float*)d_in[1];   // (512, 1024)
    const float* bias   = (const float*)d_in[2];   // (512,)
    const float* alpha  = (const float*)d_in[3];   // scalar
    const float* beta   = (const float*)d_in[4];   // scalar
    float* out = (float*)d_out;                    // (512, 512)

    prep_kernel<<<B_DIM + P_DIM, 256>>>(x, weight);
    tversky_main_kernel<<<GRID_MAIN, 256>>>();
    finalize_kernel<<<(B_DIM * P_DIM / 4) / 256, 256>>>(bias, alpha, beta, out);
}